// round 11
// baseline (speedup 1.0000x reference)
#include <cuda_runtime.h>
#include <cstdint>

// ---------------------------------------------------------------------------
// B=4096, Te=168, Td=24, X=8, H=64; 3-layer LSTM, gate order i,f,g,o.
// One CTA = 32 batch, 256 threads. Thread t: h = t&63, owns 8-batch slice
// bs=(t>>6)*8, computes all 4 gates for (h, slice). grid=128, 1 CTA/SM.
// Weights stream L2 -> SMEM via cp.async in 5 chunks/step (double-buffered);
// inner loop reads weights with LDS only (no LDG, no long-scoreboard).
// ---------------------------------------------------------------------------
#define HH      64
#define BT      32
#define NTHR    256
#define TE      168
#define TD      24
#define XDIM    8
#define BTOT    4096

typedef unsigned long long ull;

// Weight layout: row = l*32 + jb (jb = j/4 within the layer's 128-wide
// concatenated [x|h] input). g_W4[(row*4 + q)*64 + h] = float4 of the 4
// consecutive-j weights for gate q, hidden h.
#define NROWS   (3 * 32 + 2)
__device__ float4 g_W4[NROWS * 4 * 64];

// Chunk schedule: 5 chunks/step aligned to accum groups.
// C0 = L0 (x 2 rows + h 16 rows), C1/C2 = L1 halves, C3/C4 = L2 halves.
__device__ __constant__ int c_row0[5] = {0, 32, 48, 64, 80};
__device__ __constant__ int c_nf4[5]  = {18 * 256, 16 * 256, 16 * 256, 16 * 256, 16 * 256};
#define MAXF4   (18 * 256)      // 72KB chunk buffer

// ---------------------------------------------------------------------------
// f32x2 dual-FMA helpers
// ---------------------------------------------------------------------------
__device__ __forceinline__ ull ffma2(ull a, ull b, ull c) {
    ull d;
    asm("fma.rn.f32x2 %0, %1, %2, %3;" : "=l"(d) : "l"(a), "l"(b), "l"(c));
    return d;
}
__device__ __forceinline__ ull pack2(float lo, float hi) {
    ull d;
    asm("mov.b64 %0, {%1, %2};" : "=l"(d) : "f"(lo), "f"(hi));
    return d;
}
__device__ __forceinline__ float2 unpack2(ull v) {
    float lo, hi;
    asm("mov.b64 {%0, %1}, %2;" : "=f"(lo), "=f"(hi) : "l"(v));
    return make_float2(lo, hi);
}

__device__ __forceinline__ float fast_sigmoid(float x) {
    float e;
    asm("ex2.approx.f32 %0, %1;" : "=f"(e) : "f"(-1.4426950408889634f * x));
    float r;
    asm("rcp.approx.f32 %0, %1;" : "=f"(r) : "f"(1.0f + e));
    return r;
}
__device__ __forceinline__ float fast_tanh(float x) {
    return fmaf(2.0f, fast_sigmoid(2.0f * x), -1.0f);
}

// cp.async helpers
__device__ __forceinline__ void cp16(uint32_t dst, const float4* src) {
    asm volatile("cp.async.cg.shared.global [%0], [%1], 16;" :: "r"(dst), "l"(src));
}
__device__ __forceinline__ void cp_commit() { asm volatile("cp.async.commit_group;"); }
__device__ __forceinline__ void cp_wait0()  { asm volatile("cp.async.wait_group 0;"); }

// ---------------------------------------------------------------------------
// Weight prep (unchanged layout)
// ---------------------------------------------------------------------------
__global__ void prep_weights(const float* __restrict__ Wih0, const float* __restrict__ Whh0,
                             const float* __restrict__ Wih1, const float* __restrict__ Whh1,
                             const float* __restrict__ Wih2, const float* __restrict__ Whh2) {
    int idx = blockIdx.x * blockDim.x + threadIdx.x;
    const int total = NROWS * 4 * 64 * 4;
    if (idx >= total) return;
    int f   = idx & 3;
    int h   = (idx >> 2) & 63;
    int q   = (idx >> 8) & 3;
    int row = idx >> 10;
    int l   = row >> 5;
    int jb  = row & 31;
    int j   = jb * 4 + f;
    int g   = q * 64 + h;
    float val = 0.0f;
    if (l == 0) {
        if (j < 8)       val = Wih0[g * 8 + j];
        else if (j < 72) val = Whh0[g * 64 + (j - 8)];
    } else if (l == 1) {
        val = (j < 64) ? Wih1[g * 64 + j] : Whh1[g * 64 + (j - 64)];
    } else if (l == 2) {
        val = (j < 64) ? Wih2[g * 64 + j] : Whh2[g * 64 + (j - 64)];
    }
    reinterpret_cast<float*>(g_W4)[idx] = val;
}

// Dynamic SMEM layout (~198 KB)
struct Smem {
    float4 wbuf[2][MAXF4];        // 144 KB weight chunk ring
    float  hbuf[3][2][BT][HH];    // 48 KB double-buffered hidden state
    float  x_s[2][BT][XDIM];
    float  z_s[BT];
    float  vf_s[BT];
    float  rvf_s[BT];
    float  wm_s[HH];
    float  wa_s[HH];
    float  bm_ba[2];
};

// Issue cooperative cp.async of chunk cidx into wbuf[cidx&1].
__device__ __forceinline__ void issue_chunk(Smem& sm, int cidx, int t) {
    int k = cidx % 5;
    const float4* src = g_W4 + (size_t)c_row0[k] * 256;
    uint32_t d = (uint32_t)__cvta_generic_to_shared(&sm.wbuf[cidx & 1][0]);
    int n = c_nf4[k];
#pragma unroll 4
    for (int i = t; i < n; i += NTHR) cp16(d + (uint32_t)i * 16u, src + i);
    cp_commit();
}

// ---------------------------------------------------------------------------
// Accumulate NBLK 4-j blocks from an SMEM weight chunk. Weights: 4x LDS.128
// per block (conflict-free, lanes consecutive). Acts: warp-uniform LDS.128.
// ---------------------------------------------------------------------------
template <int NBLK, int STRIDE>
__device__ __forceinline__ void accum_s(ull acc[4][8], const float4* __restrict__ wp,
                                        const float* __restrict__ sbase) {
#pragma unroll 2
    for (int blk = 0; blk < NBLK; blk++) {
        float4 w0 = wp[blk * 256 + 0];
        float4 w1 = wp[blk * 256 + 64];
        float4 w2 = wp[blk * 256 + 128];
        float4 w3 = wp[blk * 256 + 192];
        ulonglong2 u0 = *reinterpret_cast<const ulonglong2*>(&w0);
        ulonglong2 u1 = *reinterpret_cast<const ulonglong2*>(&w1);
        ulonglong2 u2 = *reinterpret_cast<const ulonglong2*>(&w2);
        ulonglong2 u3 = *reinterpret_cast<const ulonglong2*>(&w3);
        const float* sp = sbase + blk * 4;
#pragma unroll
        for (int b = 0; b < 8; b++) {
            ulonglong2 a = *reinterpret_cast<const ulonglong2*>(sp + b * STRIDE);
            acc[0][b] = ffma2(u0.x, a.x, acc[0][b]);
            acc[1][b] = ffma2(u1.x, a.x, acc[1][b]);
            acc[2][b] = ffma2(u2.x, a.x, acc[2][b]);
            acc[3][b] = ffma2(u3.x, a.x, acc[3][b]);
            acc[0][b] = ffma2(u0.y, a.y, acc[0][b]);
            acc[1][b] = ffma2(u1.y, a.y, acc[1][b]);
            acc[2][b] = ffma2(u2.y, a.y, acc[2][b]);
            acc[3][b] = ffma2(u3.y, a.y, acc[3][b]);
        }
    }
}

__device__ __forceinline__ void acc_init(ull acc[4][8], const float* bl) {
#pragma unroll
    for (int q = 0; q < 4; q++) {
        ull z = pack2(bl[q], 0.0f);
#pragma unroll
        for (int k = 0; k < 8; k++) acc[q][k] = z;
    }
}

__device__ __forceinline__ void lstm_nonlin_store(ull acc[4][8], float* cst,
                                                  float (*dst)[HH], int bs, int h) {
#pragma unroll
    for (int k = 0; k < 8; k++) {
        float2 xi2 = unpack2(acc[0][k]);
        float2 xf2 = unpack2(acc[1][k]);
        float2 xg2 = unpack2(acc[2][k]);
        float2 xo2 = unpack2(acc[3][k]);
        float iv = fast_sigmoid(xi2.x + xi2.y);
        float fv = fast_sigmoid(xf2.x + xf2.y);
        float gv = fast_tanh(xg2.x + xg2.y);
        float ov = fast_sigmoid(xo2.x + xo2.y);
        float cn = fmaf(fv, cst[k], iv * gv);
        cst[k]   = cn;
        dst[bs + k][h] = ov * fast_tanh(cn);
    }
}

// One 3-layer step = 5 chunk units. Each unit: wait for its chunk (issued one
// unit earlier), barrier (also publishes prior hbuf writes), issue the next
// chunk, compute. Invariant on entry: chunk `cidx` already issued.
__device__ __forceinline__ void step3(float (&c)[3][8], const float (&bias)[3][4],
                                      int h, int bs, int pp, int& cidx, int t,
                                      Smem& sm, const float (*x_s)[XDIM]) {
    ull acc[4][8];

    // unit 0: L0 (x + h0_prev)
    cp_wait0(); __syncthreads();
    issue_chunk(sm, cidx + 1, t);
    {
        const float4* buf = &sm.wbuf[cidx & 1][0];
        acc_init(acc, bias[0]);
        accum_s<2,  XDIM>(acc, buf + h,           &x_s[bs][0]);
        accum_s<16, HH  >(acc, buf + 2 * 256 + h, &sm.hbuf[0][pp][bs][0]);
        lstm_nonlin_store(acc, c[0], sm.hbuf[0][pp ^ 1], bs, h);
    }
    cidx++;

    // unit 1: L1 first half (h0_cur)
    cp_wait0(); __syncthreads();
    issue_chunk(sm, cidx + 1, t);
    acc_init(acc, bias[1]);
    accum_s<16, HH>(acc, &sm.wbuf[cidx & 1][0] + h, &sm.hbuf[0][pp ^ 1][bs][0]);
    cidx++;

    // unit 2: L1 second half (h1_prev) + nonlin
    cp_wait0(); __syncthreads();
    issue_chunk(sm, cidx + 1, t);
    accum_s<16, HH>(acc, &sm.wbuf[cidx & 1][0] + h, &sm.hbuf[1][pp][bs][0]);
    lstm_nonlin_store(acc, c[1], sm.hbuf[1][pp ^ 1], bs, h);
    cidx++;

    // unit 3: L2 first half (h1_cur)
    cp_wait0(); __syncthreads();
    issue_chunk(sm, cidx + 1, t);
    acc_init(acc, bias[2]);
    accum_s<16, HH>(acc, &sm.wbuf[cidx & 1][0] + h, &sm.hbuf[1][pp ^ 1][bs][0]);
    cidx++;

    // unit 4: L2 second half (h2_prev) + nonlin
    cp_wait0(); __syncthreads();
    issue_chunk(sm, cidx + 1, t);
    accum_s<16, HH>(acc, &sm.wbuf[cidx & 1][0] + h, &sm.hbuf[2][pp][bs][0]);
    lstm_nonlin_store(acc, c[2], sm.hbuf[2][pp ^ 1], bs, h);
    cidx++;
}

// ---------------------------------------------------------------------------
// Main kernel: one CTA per 32-batch tile, whole encoder+decoder sequence.
// ---------------------------------------------------------------------------
__global__ void __launch_bounds__(NTHR, 1)
lstm_seq_kernel(const float* __restrict__ enc_x, const float* __restrict__ enc_z,
                const float* __restrict__ dec_x, const float* __restrict__ v,
                const float* __restrict__ eps,
                const float* __restrict__ b0, const float* __restrict__ b1,
                const float* __restrict__ b2,
                const float* __restrict__ w_m, const float* __restrict__ b_m,
                const float* __restrict__ w_a, const float* __restrict__ b_a,
                float* __restrict__ out) {
    extern __shared__ __align__(16) char smem_raw[];
    Smem& sm = *reinterpret_cast<Smem*>(smem_raw);

    const int t   = threadIdx.x;
    const int h   = t & 63;
    const int bs  = (t >> 6) * 8;
    const int b0g = blockIdx.x * BT;

    float bias[3][4];
#pragma unroll
    for (int q = 0; q < 4; q++) {
        bias[0][q] = b0[q * 64 + h];
        bias[1][q] = b1[q * 64 + h];
        bias[2][q] = b2[q * 64 + h];
    }

    for (int i = t; i < 3 * 2 * BT * HH; i += NTHR) (&sm.hbuf[0][0][0][0])[i] = 0.0f;
    if (t < HH) { sm.wm_s[t] = w_m[t]; sm.wa_s[t] = w_a[t]; }
    if (t == 0) { sm.bm_ba[0] = b_m[0]; sm.bm_ba[1] = b_a[0]; }

    float c[3][8];
#pragma unroll
    for (int l = 0; l < 3; l++)
#pragma unroll
        for (int k = 0; k < 8; k++) c[l][k] = 0.0f;

    const int bb = t >> 3, xi = t & 7;   // 256 threads = 32x8 x-loader
    int pp = 0;
    int cidx = 0;

    // Prologue: first weight chunk in flight; first x tile staged.
    issue_chunk(sm, 0, t);
    sm.x_s[0][bb][xi] = enc_x[(size_t)(b0g + bb) * (TE * XDIM) + 0 * XDIM + xi];
    __syncthreads();

    // ---------------- encoder ----------------
    for (int s = 0; s < TE; s++) {
        int cur = s & 1;
        if (s + 1 < TE)
            sm.x_s[cur ^ 1][bb][xi] =
                enc_x[(size_t)(b0g + bb) * (TE * XDIM) + (s + 1) * XDIM + xi];
        step3(c, bias, h, bs, pp, cidx, t, sm, sm.x_s[cur]);
        pp ^= 1;
    }

    // ---------------- decoder init ----------------
    if (t < BT) {
        float vf  = v[b0g + t];
        float rvf = 1.0f / vf;
        sm.vf_s[t]  = vf;
        sm.rvf_s[t] = rvf;
        sm.z_s[t]   = enc_z[(size_t)(b0g + t) * TE + (TE - 1)] * rvf;
    }
    __syncthreads();

    // ---------------- decoder ----------------
    for (int s = 0; s < TD; s++) {
        {
            float xv;
            if (xi == 0) xv = sm.z_s[bb];
            else xv = dec_x[(size_t)(b0g + bb) * (TD * (XDIM - 1)) + s * (XDIM - 1) + (xi - 1)];
            sm.x_s[0][bb][xi] = xv;
        }
        // x/z published by step3's first unit barrier
        step3(c, bias, h, bs, pp, cidx, t, sm, sm.x_s[0]);
        __syncthreads();   // h2 writes visible for the head

        if (t < BT) {
            float m  = sm.bm_ba[0];
            float ap = sm.bm_ba[1];
            const float* hrow = &sm.hbuf[2][pp ^ 1][t][0];
#pragma unroll
            for (int kk = 0; kk < HH; kk++) {
                int k = (kk + t) & 63;       // bank-conflict-free rotation
                float hv = hrow[k];
                m  = fmaf(hv, sm.wm_s[k], m);
                ap = fmaf(hv, sm.wa_s[k], ap);
            }
            float vf = sm.vf_s[t];
            m *= vf;
            float sp = fmaxf(ap, 0.0f) + log1pf(__expf(-fabsf(ap)));
            float a  = sp * vf;
            float zs = fmaf(a, eps[(size_t)(b0g + t) * TD + s], m);
            out[(size_t)(b0g + t) * TD + s] = zs;
            sm.z_s[t] = zs * sm.rvf_s[t];
        }
        pp ^= 1;
        __syncthreads();   // z_s ready before next step's x loader
    }
}

// ---------------------------------------------------------------------------
// Input order: enc_x, enc_z, dec_x, v, eps,
//   W_ih0, W_hh0, b0, W_ih1, W_hh1, b1, W_ih2, W_hh2, b2, w_m, b_m, w_a, b_a
// ---------------------------------------------------------------------------
extern "C" void kernel_launch(void* const* d_in, const int* in_sizes, int n_in,
                              void* d_out, int out_size) {
    (void)in_sizes; (void)n_in; (void)out_size;
    const float* enc_x = (const float*)d_in[0];
    const float* enc_z = (const float*)d_in[1];
    const float* dec_x = (const float*)d_in[2];
    const float* v     = (const float*)d_in[3];
    const float* eps   = (const float*)d_in[4];
    const float* Wih0  = (const float*)d_in[5];
    const float* Whh0  = (const float*)d_in[6];
    const float* b0    = (const float*)d_in[7];
    const float* Wih1  = (const float*)d_in[8];
    const float* Whh1  = (const float*)d_in[9];
    const float* b1    = (const float*)d_in[10];
    const float* Wih2  = (const float*)d_in[11];
    const float* Whh2  = (const float*)d_in[12];
    const float* b2    = (const float*)d_in[13];
    const float* w_m   = (const float*)d_in[14];
    const float* b_m   = (const float*)d_in[15];
    const float* w_a   = (const float*)d_in[16];
    const float* b_a   = (const float*)d_in[17];
    float* out = (float*)d_out;

    // >48KB dynamic smem: opt in (idempotent; capture-safe)
    cudaFuncSetAttribute(lstm_seq_kernel,
                         cudaFuncAttributeMaxDynamicSharedMemorySize,
                         (int)sizeof(Smem));

    const int total = NROWS * 4 * 64 * 4;
    prep_weights<<<(total + 255) / 256, 256>>>(Wih0, Whh0, Wih1, Whh1, Wih2, Whh2);
    lstm_seq_kernel<<<BTOT / BT, NTHR, sizeof(Smem)>>>(enc_x, enc_z, dec_x, v, eps,
                                                       b0, b1, b2, w_m, b_m, w_a, b_a, out);
}

// round 12
// speedup vs baseline: 1.0464x; 1.0464x over previous
#include <cuda_runtime.h>
#include <cstdint>

// ---------------------------------------------------------------------------
// B=4096, Te=168, Td=24, X=8, H=64; 3-layer LSTM, gate order i,f,g,o.
// One CTA = 32 batch elements, 256 threads (8 warps, barrier-convoyed).
// Thread t: h = t&63, owns an 8-batch slice bs=(t>>6)*8, computes all 4
// gates for (h, slice). grid=128, 1 CTA/SM. Cell state in registers;
// hidden state double-buffered in SMEM. Weights: LDG.128 stream with
// depth-1 register pipeline + depth-3 prefetch.global.L1 (no reg cost).
// ---------------------------------------------------------------------------
#define HH      64
#define BT      32
#define NTHR    256
#define TE      168
#define TD      24
#define XDIM    8
#define BTOT    4096

typedef unsigned long long ull;

// Contiguous weight rows (one row = one jb block = 4 j-values x 4 gates x 64 h
// = 256 float4 = 4KB):
//   L0: rows  0..17  (j 0..7 = x, j 8..71 = h0_prev)
//   L1: rows 18..49  (j 0..63 = h0_cur, 64..127 = h1_prev)
//   L2: rows 50..81  (j 0..63 = h1_cur, 64..127 = h2_prev)
//   rows 82..85 = zero pads (LDG depth-1 + prefetch depth-3 overrun)
#define NROWS   86
__device__ float4 g_W4[NROWS * 256];

// ---------------------------------------------------------------------------
// f32x2 dual-FMA helpers
// ---------------------------------------------------------------------------
__device__ __forceinline__ ull ffma2(ull a, ull b, ull c) {
    ull d;
    asm("fma.rn.f32x2 %0, %1, %2, %3;" : "=l"(d) : "l"(a), "l"(b), "l"(c));
    return d;
}
__device__ __forceinline__ ull pack2(float lo, float hi) {
    ull d;
    asm("mov.b64 %0, {%1, %2};" : "=l"(d) : "f"(lo), "f"(hi));
    return d;
}
__device__ __forceinline__ float2 unpack2(ull v) {
    float lo, hi;
    asm("mov.b64 {%0, %1}, %2;" : "=f"(lo), "=f"(hi) : "l"(v));
    return make_float2(lo, hi);
}

__device__ __forceinline__ float fast_sigmoid(float x) {
    float e;
    asm("ex2.approx.f32 %0, %1;" : "=f"(e) : "f"(-1.4426950408889634f * x));
    float r;
    asm("rcp.approx.f32 %0, %1;" : "=f"(r) : "f"(1.0f + e));
    return r;
}
__device__ __forceinline__ float fast_tanh(float x) {
    return fmaf(2.0f, fast_sigmoid(2.0f * x), -1.0f);
}

__device__ __forceinline__ void pf_l1(const void* p) {
    asm volatile("prefetch.global.L1 [%0];" :: "l"(p));
}

// ---------------------------------------------------------------------------
// Weight prep into the contiguous layout.
// g_W4[(row*4 + q)*64 + h].component[f] = W_l[gate q*64+h][ j = jb*4+f ]
// ---------------------------------------------------------------------------
__global__ void prep_weights(const float* __restrict__ Wih0, const float* __restrict__ Whh0,
                             const float* __restrict__ Wih1, const float* __restrict__ Whh1,
                             const float* __restrict__ Wih2, const float* __restrict__ Whh2) {
    int idx = blockIdx.x * blockDim.x + threadIdx.x;
    const int total = NROWS * 256 * 4;
    if (idx >= total) return;
    int f   = idx & 3;
    int h   = (idx >> 2) & 63;
    int q   = (idx >> 8) & 3;
    int row = idx >> 10;
    int g   = q * 64 + h;
    float val = 0.0f;
    if (row < 18) {                    // L0
        int j = row * 4 + f;
        if (j < 8)       val = Wih0[g * 8 + j];
        else             val = Whh0[g * 64 + (j - 8)];
    } else if (row < 50) {             // L1
        int j = (row - 18) * 4 + f;
        val = (j < 64) ? Wih1[g * 64 + j] : Whh1[g * 64 + (j - 64)];
    } else if (row < 82) {             // L2
        int j = (row - 50) * 4 + f;
        val = (j < 64) ? Wih2[g * 64 + j] : Whh2[g * 64 + (j - 64)];
    }                                   // rows 82..85: pads -> 0
    reinterpret_cast<float*>(g_W4)[idx] = val;
}

// ---------------------------------------------------------------------------
// Accumulate NBLK 4-j blocks into acc[gate][b] (f32x2 lanes sum even/odd j).
// LDG.128 x4 per block, depth-1 register pipeline; prefetch.global.L1 at
// depth 3 warms L1 so the depth-1 LDG hits (~39 cyc, hidden by 8-chain ILP).
// Rows are contiguous across groups, so blk+3 rolls into the next group.
// ---------------------------------------------------------------------------
template <int NBLK, int STRIDE>
__device__ __forceinline__ void accum_part(ull acc[4][8], const float4* __restrict__ wp,
                                           const float* __restrict__ sbase) {
    float4 w0 = __ldg(wp + 0);
    float4 w1 = __ldg(wp + 64);
    float4 w2 = __ldg(wp + 128);
    float4 w3 = __ldg(wp + 192);
#pragma unroll 2
    for (int blk = 0; blk < NBLK; blk++) {
        // L1 prefetch, depth 3 (pads/next group absorb the tail)
        const float4* pf = wp + (blk + 3) * 256;
        pf_l1(pf + 0);
        pf_l1(pf + 64);
        pf_l1(pf + 128);
        pf_l1(pf + 192);
        // depth-1 register prefetch
        const float4* np = wp + (blk + 1) * 256;
        float4 n0 = __ldg(np + 0);
        float4 n1 = __ldg(np + 64);
        float4 n2 = __ldg(np + 128);
        float4 n3 = __ldg(np + 192);

        ulonglong2 u0 = *reinterpret_cast<const ulonglong2*>(&w0);
        ulonglong2 u1 = *reinterpret_cast<const ulonglong2*>(&w1);
        ulonglong2 u2 = *reinterpret_cast<const ulonglong2*>(&w2);
        ulonglong2 u3 = *reinterpret_cast<const ulonglong2*>(&w3);
        const float* sp = sbase + blk * 4;
#pragma unroll
        for (int b = 0; b < 8; b++) {
            ulonglong2 a = *reinterpret_cast<const ulonglong2*>(sp + b * STRIDE);
            acc[0][b] = ffma2(u0.x, a.x, acc[0][b]);
            acc[1][b] = ffma2(u1.x, a.x, acc[1][b]);
            acc[2][b] = ffma2(u2.x, a.x, acc[2][b]);
            acc[3][b] = ffma2(u3.x, a.x, acc[3][b]);
            acc[0][b] = ffma2(u0.y, a.y, acc[0][b]);
            acc[1][b] = ffma2(u1.y, a.y, acc[1][b]);
            acc[2][b] = ffma2(u2.y, a.y, acc[2][b]);
            acc[3][b] = ffma2(u3.y, a.y, acc[3][b]);
        }
        w0 = n0; w1 = n1; w2 = n2; w3 = n3;
    }
}

// Dynamic SMEM layout (~50 KB)
struct Smem {
    float hbuf[3][2][BT][HH];   // double-buffered hidden state (48 KB)
    float x_s[2][BT][XDIM];     // double-buffered step input
    float z_s[BT];
    float vf_s[BT];
    float rvf_s[BT];
    float wm_s[HH];
    float wa_s[HH];
    float bm_ba[2];
};

// One 3-layer step, double-buffered hidden state (1 barrier per layer).
// Reads hb[l][pp] (prev step), writes hb[l][pp^1].
__device__ __forceinline__ void step3(float (&c)[3][8], const float (&bias)[3][4],
                                      int h, int bs, int pp,
                                      float (*hb)[2][BT][HH],
                                      const float (*x_s)[XDIM]) {
#pragma unroll
    for (int l = 0; l < 3; l++) {
        ull acc[4][8];
#pragma unroll
        for (int q = 0; q < 4; q++) {
            ull z = pack2(bias[l][q], 0.0f);
#pragma unroll
            for (int k = 0; k < 8; k++) acc[q][k] = z;
        }

        if (l == 0) {
            accum_part<2,  XDIM>(acc, g_W4 + 0 * 256 + h,  &x_s[bs][0]);
            accum_part<16, HH  >(acc, g_W4 + 2 * 256 + h,  &hb[0][pp][bs][0]);
        } else if (l == 1) {
            accum_part<16, HH  >(acc, g_W4 + 18 * 256 + h, &hb[0][pp ^ 1][bs][0]);
            accum_part<16, HH  >(acc, g_W4 + 34 * 256 + h, &hb[1][pp][bs][0]);
        } else {
            accum_part<16, HH  >(acc, g_W4 + 50 * 256 + h, &hb[1][pp ^ 1][bs][0]);
            accum_part<16, HH  >(acc, g_W4 + 66 * 256 + h, &hb[2][pp][bs][0]);
        }

        float hv[8];
#pragma unroll
        for (int k = 0; k < 8; k++) {
            float2 xi2 = unpack2(acc[0][k]);
            float2 xf2 = unpack2(acc[1][k]);
            float2 xg2 = unpack2(acc[2][k]);
            float2 xo2 = unpack2(acc[3][k]);
            float iv = fast_sigmoid(xi2.x + xi2.y);
            float fv = fast_sigmoid(xf2.x + xf2.y);
            float gv = fast_tanh(xg2.x + xg2.y);
            float ov = fast_sigmoid(xo2.x + xo2.y);
            float cn = fmaf(fv, c[l][k], iv * gv);
            c[l][k]  = cn;
            hv[k]    = ov * fast_tanh(cn);
        }
#pragma unroll
        for (int k = 0; k < 8; k++) hb[l][pp ^ 1][bs + k][h] = hv[k];
        __syncthreads();   // layer-l outputs visible; old buffer free
    }
}

// ---------------------------------------------------------------------------
// Main kernel: one CTA per 32-batch tile, whole encoder+decoder sequence.
// ---------------------------------------------------------------------------
__global__ void __launch_bounds__(NTHR, 1)
lstm_seq_kernel(const float* __restrict__ enc_x, const float* __restrict__ enc_z,
                const float* __restrict__ dec_x, const float* __restrict__ v,
                const float* __restrict__ eps,
                const float* __restrict__ b0, const float* __restrict__ b1,
                const float* __restrict__ b2,
                const float* __restrict__ w_m, const float* __restrict__ b_m,
                const float* __restrict__ w_a, const float* __restrict__ b_a,
                float* __restrict__ out) {
    extern __shared__ __align__(16) char smem_raw[];
    Smem& sm = *reinterpret_cast<Smem*>(smem_raw);

    const int t   = threadIdx.x;
    const int h   = t & 63;
    const int bs  = (t >> 6) * 8;
    const int b0g = blockIdx.x * BT;

    float bias[3][4];
#pragma unroll
    for (int q = 0; q < 4; q++) {
        bias[0][q] = b0[q * 64 + h];
        bias[1][q] = b1[q * 64 + h];
        bias[2][q] = b2[q * 64 + h];
    }

    for (int i = t; i < 3 * 2 * BT * HH; i += NTHR) (&sm.hbuf[0][0][0][0])[i] = 0.0f;
    if (t < HH) { sm.wm_s[t] = w_m[t]; sm.wa_s[t] = w_a[t]; }
    if (t == 0) { sm.bm_ba[0] = b_m[0]; sm.bm_ba[1] = b_a[0]; }

    float c[3][8];
#pragma unroll
    for (int l = 0; l < 3; l++)
#pragma unroll
        for (int k = 0; k < 8; k++) c[l][k] = 0.0f;

    const int bb = t >> 3, xi = t & 7;   // 256 threads = 32x8 x-loader
    int pp = 0;

    // ---------------- encoder ----------------
    sm.x_s[0][bb][xi] = enc_x[(size_t)(b0g + bb) * (TE * XDIM) + 0 * XDIM + xi];
    __syncthreads();
    for (int s = 0; s < TE; s++) {
        int cur = s & 1;
        if (s + 1 < TE)
            sm.x_s[cur ^ 1][bb][xi] =
                enc_x[(size_t)(b0g + bb) * (TE * XDIM) + (s + 1) * XDIM + xi];
        step3(c, bias, h, bs, pp, sm.hbuf, sm.x_s[cur]);
        pp ^= 1;
    }

    // ---------------- decoder init ----------------
    if (t < BT) {
        float vf  = v[b0g + t];
        float rvf = 1.0f / vf;
        sm.vf_s[t]  = vf;
        sm.rvf_s[t] = rvf;
        sm.z_s[t]   = enc_z[(size_t)(b0g + t) * TE + (TE - 1)] * rvf;
    }
    __syncthreads();

    // ---------------- decoder ----------------
    for (int s = 0; s < TD; s++) {
        {
            float xv;
            if (xi == 0) xv = sm.z_s[bb];
            else xv = dec_x[(size_t)(b0g + bb) * (TD * (XDIM - 1)) + s * (XDIM - 1) + (xi - 1)];
            sm.x_s[0][bb][xi] = xv;
        }
        __syncthreads();

        step3(c, bias, h, bs, pp, sm.hbuf, sm.x_s[0]);

        if (t < BT) {
            float m  = sm.bm_ba[0];
            float ap = sm.bm_ba[1];
            const float* hrow = &sm.hbuf[2][pp ^ 1][t][0];
#pragma unroll
            for (int kk = 0; kk < HH; kk++) {
                int k = (kk + t) & 63;       // bank-conflict-free rotation
                float hv = hrow[k];
                m  = fmaf(hv, sm.wm_s[k], m);
                ap = fmaf(hv, sm.wa_s[k], ap);
            }
            float vf = sm.vf_s[t];
            m *= vf;
            float sp = fmaxf(ap, 0.0f) + log1pf(__expf(-fabsf(ap)));
            float a  = sp * vf;
            float zs = fmaf(a, eps[(size_t)(b0g + t) * TD + s], m);
            out[(size_t)(b0g + t) * TD + s] = zs;
            sm.z_s[t] = zs * sm.rvf_s[t];
        }
        pp ^= 1;
        __syncthreads();   // z_s ready before next step's x loader
    }
}

// ---------------------------------------------------------------------------
// Input order: enc_x, enc_z, dec_x, v, eps,
//   W_ih0, W_hh0, b0, W_ih1, W_hh1, b1, W_ih2, W_hh2, b2, w_m, b_m, w_a, b_a
// ---------------------------------------------------------------------------
extern "C" void kernel_launch(void* const* d_in, const int* in_sizes, int n_in,
                              void* d_out, int out_size) {
    (void)in_sizes; (void)n_in; (void)out_size;
    const float* enc_x = (const float*)d_in[0];
    const float* enc_z = (const float*)d_in[1];
    const float* dec_x = (const float*)d_in[2];
    const float* v     = (const float*)d_in[3];
    const float* eps   = (const float*)d_in[4];
    const float* Wih0  = (const float*)d_in[5];
    const float* Whh0  = (const float*)d_in[6];
    const float* b0    = (const float*)d_in[7];
    const float* Wih1  = (const float*)d_in[8];
    const float* Whh1  = (const float*)d_in[9];
    const float* b1    = (const float*)d_in[10];
    const float* Wih2  = (const float*)d_in[11];
    const float* Whh2  = (const float*)d_in[12];
    const float* b2    = (const float*)d_in[13];
    const float* w_m   = (const float*)d_in[14];
    const float* b_m   = (const float*)d_in[15];
    const float* w_a   = (const float*)d_in[16];
    const float* b_a   = (const float*)d_in[17];
    float* out = (float*)d_out;

    // >48KB dynamic smem: opt in (idempotent; capture-safe)
    cudaFuncSetAttribute(lstm_seq_kernel,
                         cudaFuncAttributeMaxDynamicSharedMemorySize,
                         (int)sizeof(Smem));

    const int total = NROWS * 256 * 4;
    prep_weights<<<(total + 255) / 256, 256>>>(Wih0, Whh0, Wih1, Whh1, Wih2, Whh2);
    lstm_seq_kernel<<<BTOT / BT, NTHR, sizeof(Smem)>>>(enc_x, enc_z, dec_x, v, eps,
                                                       b0, b1, b2, w_m, b_m, w_a, b_a, out);
}

// round 13
// speedup vs baseline: 1.0488x; 1.0023x over previous
#include <cuda_runtime.h>
#include <cstdint>

// ---------------------------------------------------------------------------
// B=4096, Te=168, Td=24, X=8, H=64; 3-layer LSTM, gate order i,f,g,o.
// One CTA = 32 batch elements, 256 threads (8 warps, barrier-convoyed).
// Thread t: h = t&63, owns an 8-batch slice bs=(t>>6)*8, computes all 4
// gates for (h, slice). grid=128, 1 CTA/SM. Cell state in registers;
// hidden state double-buffered in SMEM. Weights: LDG.128 stream with
// depth-1 register pipeline + depth-3 prefetch.global.L1 (no reg cost).
// ---------------------------------------------------------------------------
#define HH      64
#define BT      32
#define NTHR    256
#define TE      168
#define TD      24
#define XDIM    8
#define BTOT    4096

typedef unsigned long long ull;

// Contiguous weight rows (one row = one jb block = 4 j-values x 4 gates x 64 h
// = 256 float4 = 4KB):
//   L0: rows  0..17  (j 0..7 = x, j 8..71 = h0_prev)
//   L1: rows 18..49  (j 0..63 = h0_cur, 64..127 = h1_prev)
//   L2: rows 50..81  (j 0..63 = h1_cur, 64..127 = h2_prev)
//   rows 82..85 = zero pads (LDG depth-1 + prefetch depth-3 overrun)
#define NROWS   86
__device__ float4 g_W4[NROWS * 256];

// ---------------------------------------------------------------------------
// f32x2 dual-FMA helpers
// ---------------------------------------------------------------------------
__device__ __forceinline__ ull ffma2(ull a, ull b, ull c) {
    ull d;
    asm("fma.rn.f32x2 %0, %1, %2, %3;" : "=l"(d) : "l"(a), "l"(b), "l"(c));
    return d;
}
__device__ __forceinline__ ull pack2(float lo, float hi) {
    ull d;
    asm("mov.b64 %0, {%1, %2};" : "=l"(d) : "f"(lo), "f"(hi));
    return d;
}
__device__ __forceinline__ float2 unpack2(ull v) {
    float lo, hi;
    asm("mov.b64 {%0, %1}, %2;" : "=f"(lo), "=f"(hi) : "l"(v));
    return make_float2(lo, hi);
}

__device__ __forceinline__ float fast_sigmoid(float x) {
    float e;
    asm("ex2.approx.f32 %0, %1;" : "=f"(e) : "f"(-1.4426950408889634f * x));
    float r;
    asm("rcp.approx.f32 %0, %1;" : "=f"(r) : "f"(1.0f + e));
    return r;
}
__device__ __forceinline__ float fast_tanh(float x) {
    return fmaf(2.0f, fast_sigmoid(2.0f * x), -1.0f);
}

__device__ __forceinline__ void pf_l1(const void* p) {
    asm volatile("prefetch.global.L1 [%0];" :: "l"(p));
}

// ---------------------------------------------------------------------------
// Weight prep into the contiguous layout.
// g_W4[(row*4 + q)*64 + h].component[f] = W_l[gate q*64+h][ j = jb*4+f ]
// ---------------------------------------------------------------------------
__global__ void prep_weights(const float* __restrict__ Wih0, const float* __restrict__ Whh0,
                             const float* __restrict__ Wih1, const float* __restrict__ Whh1,
                             const float* __restrict__ Wih2, const float* __restrict__ Whh2) {
    int idx = blockIdx.x * blockDim.x + threadIdx.x;
    const int total = NROWS * 256 * 4;
    if (idx >= total) return;
    int f   = idx & 3;
    int h   = (idx >> 2) & 63;
    int q   = (idx >> 8) & 3;
    int row = idx >> 10;
    int g   = q * 64 + h;
    float val = 0.0f;
    if (row < 18) {                    // L0
        int j = row * 4 + f;
        if (j < 8)       val = Wih0[g * 8 + j];
        else             val = Whh0[g * 64 + (j - 8)];
    } else if (row < 50) {             // L1
        int j = (row - 18) * 4 + f;
        val = (j < 64) ? Wih1[g * 64 + j] : Whh1[g * 64 + (j - 64)];
    } else if (row < 82) {             // L2
        int j = (row - 50) * 4 + f;
        val = (j < 64) ? Wih2[g * 64 + j] : Whh2[g * 64 + (j - 64)];
    }                                   // rows 82..85: pads -> 0
    reinterpret_cast<float*>(g_W4)[idx] = val;
}

// ---------------------------------------------------------------------------
// Accumulate NBLK 4-j blocks into acc[gate][b] (f32x2 lanes sum even/odd j).
// LDG.128 x4 per block, depth-1 register pipeline; prefetch.global.L1 at
// depth 3 warms L1 so the depth-1 LDG hits (~39 cyc, hidden by 8-chain ILP).
// Rows are contiguous across groups, so blk+3 rolls into the next group.
// ---------------------------------------------------------------------------
template <int NBLK, int STRIDE>
__device__ __forceinline__ void accum_part(ull acc[4][8], const float4* __restrict__ wp,
                                           const float* __restrict__ sbase) {
    float4 w0 = __ldg(wp + 0);
    float4 w1 = __ldg(wp + 64);
    float4 w2 = __ldg(wp + 128);
    float4 w3 = __ldg(wp + 192);
#pragma unroll 2
    for (int blk = 0; blk < NBLK; blk++) {
        // L1 prefetch, depth 3 (pads/next group absorb the tail)
        const float4* pf = wp + (blk + 3) * 256;
        pf_l1(pf + 0);
        pf_l1(pf + 64);
        pf_l1(pf + 128);
        pf_l1(pf + 192);
        // depth-1 register prefetch
        const float4* np = wp + (blk + 1) * 256;
        float4 n0 = __ldg(np + 0);
        float4 n1 = __ldg(np + 64);
        float4 n2 = __ldg(np + 128);
        float4 n3 = __ldg(np + 192);

        ulonglong2 u0 = *reinterpret_cast<const ulonglong2*>(&w0);
        ulonglong2 u1 = *reinterpret_cast<const ulonglong2*>(&w1);
        ulonglong2 u2 = *reinterpret_cast<const ulonglong2*>(&w2);
        ulonglong2 u3 = *reinterpret_cast<const ulonglong2*>(&w3);
        const float* sp = sbase + blk * 4;
#pragma unroll
        for (int b = 0; b < 8; b++) {
            ulonglong2 a = *reinterpret_cast<const ulonglong2*>(sp + b * STRIDE);
            acc[0][b] = ffma2(u0.x, a.x, acc[0][b]);
            acc[1][b] = ffma2(u1.x, a.x, acc[1][b]);
            acc[2][b] = ffma2(u2.x, a.x, acc[2][b]);
            acc[3][b] = ffma2(u3.x, a.x, acc[3][b]);
            acc[0][b] = ffma2(u0.y, a.y, acc[0][b]);
            acc[1][b] = ffma2(u1.y, a.y, acc[1][b]);
            acc[2][b] = ffma2(u2.y, a.y, acc[2][b]);
            acc[3][b] = ffma2(u3.y, a.y, acc[3][b]);
        }
        w0 = n0; w1 = n1; w2 = n2; w3 = n3;
    }
}

// Dynamic SMEM layout (~50 KB)
struct Smem {
    float hbuf[3][2][BT][HH];   // double-buffered hidden state (48 KB)
    float x_s[2][BT][XDIM];     // double-buffered step input
    float z_s[BT];
    float vf_s[BT];
    float rvf_s[BT];
    float wm_s[HH];
    float wa_s[HH];
    float bm_ba[2];
};

// One 3-layer step, double-buffered hidden state (1 barrier per layer).
// Reads hb[l][pp] (prev step), writes hb[l][pp^1].
__device__ __forceinline__ void step3(float (&c)[3][8], const float (&bias)[3][4],
                                      int h, int bs, int pp,
                                      float (*hb)[2][BT][HH],
                                      const float (*x_s)[XDIM]) {
#pragma unroll
    for (int l = 0; l < 3; l++) {
        ull acc[4][8];
#pragma unroll
        for (int q = 0; q < 4; q++) {
            ull z = pack2(bias[l][q], 0.0f);
#pragma unroll
            for (int k = 0; k < 8; k++) acc[q][k] = z;
        }

        if (l == 0) {
            accum_part<2,  XDIM>(acc, g_W4 + 0 * 256 + h,  &x_s[bs][0]);
            accum_part<16, HH  >(acc, g_W4 + 2 * 256 + h,  &hb[0][pp][bs][0]);
        } else if (l == 1) {
            accum_part<16, HH  >(acc, g_W4 + 18 * 256 + h, &hb[0][pp ^ 1][bs][0]);
            accum_part<16, HH  >(acc, g_W4 + 34 * 256 + h, &hb[1][pp][bs][0]);
        } else {
            accum_part<16, HH  >(acc, g_W4 + 50 * 256 + h, &hb[1][pp ^ 1][bs][0]);
            accum_part<16, HH  >(acc, g_W4 + 66 * 256 + h, &hb[2][pp][bs][0]);
        }

        float hv[8];
#pragma unroll
        for (int k = 0; k < 8; k++) {
            float2 xi2 = unpack2(acc[0][k]);
            float2 xf2 = unpack2(acc[1][k]);
            float2 xg2 = unpack2(acc[2][k]);
            float2 xo2 = unpack2(acc[3][k]);
            float iv = fast_sigmoid(xi2.x + xi2.y);
            float fv = fast_sigmoid(xf2.x + xf2.y);
            float gv = fast_tanh(xg2.x + xg2.y);
            float ov = fast_sigmoid(xo2.x + xo2.y);
            float cn = fmaf(fv, c[l][k], iv * gv);
            c[l][k]  = cn;
            hv[k]    = ov * fast_tanh(cn);
        }
#pragma unroll
        for (int k = 0; k < 8; k++) hb[l][pp ^ 1][bs + k][h] = hv[k];
        __syncthreads();   // layer-l outputs visible; old buffer free
    }
}

// ---------------------------------------------------------------------------
// Main kernel: one CTA per 32-batch tile, whole encoder+decoder sequence.
// ---------------------------------------------------------------------------
__global__ void __launch_bounds__(NTHR, 1)
lstm_seq_kernel(const float* __restrict__ enc_x, const float* __restrict__ enc_z,
                const float* __restrict__ dec_x, const float* __restrict__ v,
                const float* __restrict__ eps,
                const float* __restrict__ b0, const float* __restrict__ b1,
                const float* __restrict__ b2,
                const float* __restrict__ w_m, const float* __restrict__ b_m,
                const float* __restrict__ w_a, const float* __restrict__ b_a,
                float* __restrict__ out) {
    extern __shared__ __align__(16) char smem_raw[];
    Smem& sm = *reinterpret_cast<Smem*>(smem_raw);

    const int t   = threadIdx.x;
    const int h   = t & 63;
    const int bs  = (t >> 6) * 8;
    const int b0g = blockIdx.x * BT;

    float bias[3][4];
#pragma unroll
    for (int q = 0; q < 4; q++) {
        bias[0][q] = b0[q * 64 + h];
        bias[1][q] = b1[q * 64 + h];
        bias[2][q] = b2[q * 64 + h];
    }

    for (int i = t; i < 3 * 2 * BT * HH; i += NTHR) (&sm.hbuf[0][0][0][0])[i] = 0.0f;
    if (t < HH) { sm.wm_s[t] = w_m[t]; sm.wa_s[t] = w_a[t]; }
    if (t == 0) { sm.bm_ba[0] = b_m[0]; sm.bm_ba[1] = b_a[0]; }

    float c[3][8];
#pragma unroll
    for (int l = 0; l < 3; l++)
#pragma unroll
        for (int k = 0; k < 8; k++) c[l][k] = 0.0f;

    const int bb = t >> 3, xi = t & 7;   // 256 threads = 32x8 x-loader
    int pp = 0;

    // ---------------- encoder ----------------
    sm.x_s[0][bb][xi] = enc_x[(size_t)(b0g + bb) * (TE * XDIM) + 0 * XDIM + xi];
    __syncthreads();
    for (int s = 0; s < TE; s++) {
        int cur = s & 1;
        if (s + 1 < TE)
            sm.x_s[cur ^ 1][bb][xi] =
                enc_x[(size_t)(b0g + bb) * (TE * XDIM) + (s + 1) * XDIM + xi];
        step3(c, bias, h, bs, pp, sm.hbuf, sm.x_s[cur]);
        pp ^= 1;
    }

    // ---------------- decoder init ----------------
    if (t < BT) {
        float vf  = v[b0g + t];
        float rvf = 1.0f / vf;
        sm.vf_s[t]  = vf;
        sm.rvf_s[t] = rvf;
        sm.z_s[t]   = enc_z[(size_t)(b0g + t) * TE + (TE - 1)] * rvf;
    }
    __syncthreads();

    // ---------------- decoder ----------------
    for (int s = 0; s < TD; s++) {
        {
            float xv;
            if (xi == 0) xv = sm.z_s[bb];
            else xv = dec_x[(size_t)(b0g + bb) * (TD * (XDIM - 1)) + s * (XDIM - 1) + (xi - 1)];
            sm.x_s[0][bb][xi] = xv;
        }
        __syncthreads();

        step3(c, bias, h, bs, pp, sm.hbuf, sm.x_s[0]);

        if (t < BT) {
            float m  = sm.bm_ba[0];
            float ap = sm.bm_ba[1];
            const float* hrow = &sm.hbuf[2][pp ^ 1][t][0];
#pragma unroll
            for (int kk = 0; kk < HH; kk++) {
                int k = (kk + t) & 63;       // bank-conflict-free rotation
                float hv = hrow[k];
                m  = fmaf(hv, sm.wm_s[k], m);
                ap = fmaf(hv, sm.wa_s[k], ap);
            }
            float vf = sm.vf_s[t];
            m *= vf;
            float sp = fmaxf(ap, 0.0f) + log1pf(__expf(-fabsf(ap)));
            float a  = sp * vf;
            float zs = fmaf(a, eps[(size_t)(b0g + t) * TD + s], m);
            out[(size_t)(b0g + t) * TD + s] = zs;
            sm.z_s[t] = zs * sm.rvf_s[t];
        }
        pp ^= 1;
        __syncthreads();   // z_s ready before next step's x loader
    }
}

// ---------------------------------------------------------------------------
// Input order: enc_x, enc_z, dec_x, v, eps,
//   W_ih0, W_hh0, b0, W_ih1, W_hh1, b1, W_ih2, W_hh2, b2, w_m, b_m, w_a, b_a
// ---------------------------------------------------------------------------
extern "C" void kernel_launch(void* const* d_in, const int* in_sizes, int n_in,
                              void* d_out, int out_size) {
    (void)in_sizes; (void)n_in; (void)out_size;
    const float* enc_x = (const float*)d_in[0];
    const float* enc_z = (const float*)d_in[1];
    const float* dec_x = (const float*)d_in[2];
    const float* v     = (const float*)d_in[3];
    const float* eps   = (const float*)d_in[4];
    const float* Wih0  = (const float*)d_in[5];
    const float* Whh0  = (const float*)d_in[6];
    const float* b0    = (const float*)d_in[7];
    const float* Wih1  = (const float*)d_in[8];
    const float* Whh1  = (const float*)d_in[9];
    const float* b1    = (const float*)d_in[10];
    const float* Wih2  = (const float*)d_in[11];
    const float* Whh2  = (const float*)d_in[12];
    const float* b2    = (const float*)d_in[13];
    const float* w_m   = (const float*)d_in[14];
    const float* b_m   = (const float*)d_in[15];
    const float* w_a   = (const float*)d_in[16];
    const float* b_a   = (const float*)d_in[17];
    float* out = (float*)d_out;

    // >48KB dynamic smem: opt in (idempotent; capture-safe)
    cudaFuncSetAttribute(lstm_seq_kernel,
                         cudaFuncAttributeMaxDynamicSharedMemorySize,
                         (int)sizeof(Smem));

    const int total = NROWS * 256 * 4;
    prep_weights<<<(total + 255) / 256, 256>>>(Wih0, Whh0, Wih1, Whh1, Wih2, Whh2);
    lstm_seq_kernel<<<BTOT / BT, NTHR, sizeof(Smem)>>>(enc_x, enc_z, dec_x, v, eps,
                                                       b0, b1, b2, w_m, b_m, w_a, b_a, out);
}

// round 14
// speedup vs baseline: 1.0498x; 1.0010x over previous
#include <cuda_runtime.h>
#include <cstdint>

// ---------------------------------------------------------------------------
// B=4096, Te=168, Td=24, X=8, H=64; 3-layer LSTM, gate order i,f,g,o.
// One CTA = 32 batch elements, 256 threads (8 warps, barrier-convoyed).
// Thread t: h = t&63, owns an 8-batch slice bs=(t>>6)*8, computes all 4
// gates for (h, slice). grid=128, 1 CTA/SM. Cell state in registers;
// hidden state double-buffered in SMEM. Weights: LDG.128 stream with
// depth-1 register pipeline + depth-3 prefetch.global.L1 (no reg cost).
// ---------------------------------------------------------------------------
#define HH      64
#define BT      32
#define NTHR    256
#define TE      168
#define TD      24
#define XDIM    8
#define BTOT    4096

typedef unsigned long long ull;

// Contiguous weight rows (one row = one jb block = 4 j-values x 4 gates x 64 h
// = 256 float4 = 4KB):
//   L0: rows  0..17  (j 0..7 = x, j 8..71 = h0_prev)
//   L1: rows 18..49  (j 0..63 = h0_cur, 64..127 = h1_prev)
//   L2: rows 50..81  (j 0..63 = h1_cur, 64..127 = h2_prev)
//   rows 82..85 = zero pads (LDG depth-1 + prefetch depth-3 overrun)
#define NROWS   86
__device__ float4 g_W4[NROWS * 256];

// ---------------------------------------------------------------------------
// f32x2 dual-FMA helpers
// ---------------------------------------------------------------------------
__device__ __forceinline__ ull ffma2(ull a, ull b, ull c) {
    ull d;
    asm("fma.rn.f32x2 %0, %1, %2, %3;" : "=l"(d) : "l"(a), "l"(b), "l"(c));
    return d;
}
__device__ __forceinline__ ull pack2(float lo, float hi) {
    ull d;
    asm("mov.b64 %0, {%1, %2};" : "=l"(d) : "f"(lo), "f"(hi));
    return d;
}
__device__ __forceinline__ float2 unpack2(ull v) {
    float lo, hi;
    asm("mov.b64 {%0, %1}, %2;" : "=f"(lo), "=f"(hi) : "l"(v));
    return make_float2(lo, hi);
}

__device__ __forceinline__ float fast_sigmoid(float x) {
    float e;
    asm("ex2.approx.f32 %0, %1;" : "=f"(e) : "f"(-1.4426950408889634f * x));
    float r;
    asm("rcp.approx.f32 %0, %1;" : "=f"(r) : "f"(1.0f + e));
    return r;
}
__device__ __forceinline__ float fast_tanh(float x) {
    return fmaf(2.0f, fast_sigmoid(2.0f * x), -1.0f);
}

__device__ __forceinline__ void pf_l1(const void* p) {
    asm volatile("prefetch.global.L1 [%0];" :: "l"(p));
}

// ---------------------------------------------------------------------------
// Weight prep into the contiguous layout.
// g_W4[(row*4 + q)*64 + h].component[f] = W_l[gate q*64+h][ j = jb*4+f ]
// ---------------------------------------------------------------------------
__global__ void prep_weights(const float* __restrict__ Wih0, const float* __restrict__ Whh0,
                             const float* __restrict__ Wih1, const float* __restrict__ Whh1,
                             const float* __restrict__ Wih2, const float* __restrict__ Whh2) {
    int idx = blockIdx.x * blockDim.x + threadIdx.x;
    const int total = NROWS * 256 * 4;
    if (idx >= total) return;
    int f   = idx & 3;
    int h   = (idx >> 2) & 63;
    int q   = (idx >> 8) & 3;
    int row = idx >> 10;
    int g   = q * 64 + h;
    float val = 0.0f;
    if (row < 18) {                    // L0
        int j = row * 4 + f;
        if (j < 8)       val = Wih0[g * 8 + j];
        else             val = Whh0[g * 64 + (j - 8)];
    } else if (row < 50) {             // L1
        int j = (row - 18) * 4 + f;
        val = (j < 64) ? Wih1[g * 64 + j] : Whh1[g * 64 + (j - 64)];
    } else if (row < 82) {             // L2
        int j = (row - 50) * 4 + f;
        val = (j < 64) ? Wih2[g * 64 + j] : Whh2[g * 64 + (j - 64)];
    }                                   // rows 82..85: pads -> 0
    reinterpret_cast<float*>(g_W4)[idx] = val;
}

// ---------------------------------------------------------------------------
// Accumulate NBLK 4-j blocks into acc[gate][b] (f32x2 lanes sum even/odd j).
// LDG.128 x4 per block, depth-1 register pipeline; prefetch.global.L1 at
// depth 3 warms L1 so the depth-1 LDG hits (~39 cyc, hidden by 8-chain ILP).
// Rows are contiguous across groups, so blk+3 rolls into the next group.
// ---------------------------------------------------------------------------
template <int NBLK, int STRIDE>
__device__ __forceinline__ void accum_part(ull acc[4][8], const float4* __restrict__ wp,
                                           const float* __restrict__ sbase) {
    float4 w0 = __ldg(wp + 0);
    float4 w1 = __ldg(wp + 64);
    float4 w2 = __ldg(wp + 128);
    float4 w3 = __ldg(wp + 192);
#pragma unroll 2
    for (int blk = 0; blk < NBLK; blk++) {
        // L1 prefetch, depth 3 (pads/next group absorb the tail)
        const float4* pf = wp + (blk + 3) * 256;
        pf_l1(pf + 0);
        pf_l1(pf + 64);
        pf_l1(pf + 128);
        pf_l1(pf + 192);
        // depth-1 register prefetch
        const float4* np = wp + (blk + 1) * 256;
        float4 n0 = __ldg(np + 0);
        float4 n1 = __ldg(np + 64);
        float4 n2 = __ldg(np + 128);
        float4 n3 = __ldg(np + 192);

        ulonglong2 u0 = *reinterpret_cast<const ulonglong2*>(&w0);
        ulonglong2 u1 = *reinterpret_cast<const ulonglong2*>(&w1);
        ulonglong2 u2 = *reinterpret_cast<const ulonglong2*>(&w2);
        ulonglong2 u3 = *reinterpret_cast<const ulonglong2*>(&w3);
        const float* sp = sbase + blk * 4;
#pragma unroll
        for (int b = 0; b < 8; b++) {
            ulonglong2 a = *reinterpret_cast<const ulonglong2*>(sp + b * STRIDE);
            acc[0][b] = ffma2(u0.x, a.x, acc[0][b]);
            acc[1][b] = ffma2(u1.x, a.x, acc[1][b]);
            acc[2][b] = ffma2(u2.x, a.x, acc[2][b]);
            acc[3][b] = ffma2(u3.x, a.x, acc[3][b]);
            acc[0][b] = ffma2(u0.y, a.y, acc[0][b]);
            acc[1][b] = ffma2(u1.y, a.y, acc[1][b]);
            acc[2][b] = ffma2(u2.y, a.y, acc[2][b]);
            acc[3][b] = ffma2(u3.y, a.y, acc[3][b]);
        }
        w0 = n0; w1 = n1; w2 = n2; w3 = n3;
    }
}

// Dynamic SMEM layout (~50 KB)
struct Smem {
    float hbuf[3][2][BT][HH];   // double-buffered hidden state (48 KB)
    float x_s[2][BT][XDIM];     // double-buffered step input
    float z_s[BT];
    float vf_s[BT];
    float rvf_s[BT];
    float wm_s[HH];
    float wa_s[HH];
    float bm_ba[2];
};

// One 3-layer step, double-buffered hidden state (1 barrier per layer).
// Reads hb[l][pp] (prev step), writes hb[l][pp^1].
__device__ __forceinline__ void step3(float (&c)[3][8], const float (&bias)[3][4],
                                      int h, int bs, int pp,
                                      float (*hb)[2][BT][HH],
                                      const float (*x_s)[XDIM]) {
#pragma unroll
    for (int l = 0; l < 3; l++) {
        ull acc[4][8];
#pragma unroll
        for (int q = 0; q < 4; q++) {
            ull z = pack2(bias[l][q], 0.0f);
#pragma unroll
            for (int k = 0; k < 8; k++) acc[q][k] = z;
        }

        if (l == 0) {
            accum_part<2,  XDIM>(acc, g_W4 + 0 * 256 + h,  &x_s[bs][0]);
            accum_part<16, HH  >(acc, g_W4 + 2 * 256 + h,  &hb[0][pp][bs][0]);
        } else if (l == 1) {
            accum_part<16, HH  >(acc, g_W4 + 18 * 256 + h, &hb[0][pp ^ 1][bs][0]);
            accum_part<16, HH  >(acc, g_W4 + 34 * 256 + h, &hb[1][pp][bs][0]);
        } else {
            accum_part<16, HH  >(acc, g_W4 + 50 * 256 + h, &hb[1][pp ^ 1][bs][0]);
            accum_part<16, HH  >(acc, g_W4 + 66 * 256 + h, &hb[2][pp][bs][0]);
        }

        float hv[8];
#pragma unroll
        for (int k = 0; k < 8; k++) {
            float2 xi2 = unpack2(acc[0][k]);
            float2 xf2 = unpack2(acc[1][k]);
            float2 xg2 = unpack2(acc[2][k]);
            float2 xo2 = unpack2(acc[3][k]);
            float iv = fast_sigmoid(xi2.x + xi2.y);
            float fv = fast_sigmoid(xf2.x + xf2.y);
            float gv = fast_tanh(xg2.x + xg2.y);
            float ov = fast_sigmoid(xo2.x + xo2.y);
            float cn = fmaf(fv, c[l][k], iv * gv);
            c[l][k]  = cn;
            hv[k]    = ov * fast_tanh(cn);
        }
#pragma unroll
        for (int k = 0; k < 8; k++) hb[l][pp ^ 1][bs + k][h] = hv[k];
        __syncthreads();   // layer-l outputs visible; old buffer free
    }
}

// ---------------------------------------------------------------------------
// Main kernel: one CTA per 32-batch tile, whole encoder+decoder sequence.
// ---------------------------------------------------------------------------
__global__ void __launch_bounds__(NTHR, 1)
lstm_seq_kernel(const float* __restrict__ enc_x, const float* __restrict__ enc_z,
                const float* __restrict__ dec_x, const float* __restrict__ v,
                const float* __restrict__ eps,
                const float* __restrict__ b0, const float* __restrict__ b1,
                const float* __restrict__ b2,
                const float* __restrict__ w_m, const float* __restrict__ b_m,
                const float* __restrict__ w_a, const float* __restrict__ b_a,
                float* __restrict__ out) {
    extern __shared__ __align__(16) char smem_raw[];
    Smem& sm = *reinterpret_cast<Smem*>(smem_raw);

    const int t   = threadIdx.x;
    const int h   = t & 63;
    const int bs  = (t >> 6) * 8;
    const int b0g = blockIdx.x * BT;

    float bias[3][4];
#pragma unroll
    for (int q = 0; q < 4; q++) {
        bias[0][q] = b0[q * 64 + h];
        bias[1][q] = b1[q * 64 + h];
        bias[2][q] = b2[q * 64 + h];
    }

    for (int i = t; i < 3 * 2 * BT * HH; i += NTHR) (&sm.hbuf[0][0][0][0])[i] = 0.0f;
    if (t < HH) { sm.wm_s[t] = w_m[t]; sm.wa_s[t] = w_a[t]; }
    if (t == 0) { sm.bm_ba[0] = b_m[0]; sm.bm_ba[1] = b_a[0]; }

    float c[3][8];
#pragma unroll
    for (int l = 0; l < 3; l++)
#pragma unroll
        for (int k = 0; k < 8; k++) c[l][k] = 0.0f;

    const int bb = t >> 3, xi = t & 7;   // 256 threads = 32x8 x-loader
    int pp = 0;

    // ---------------- encoder ----------------
    sm.x_s[0][bb][xi] = enc_x[(size_t)(b0g + bb) * (TE * XDIM) + 0 * XDIM + xi];
    __syncthreads();
    for (int s = 0; s < TE; s++) {
        int cur = s & 1;
        if (s + 1 < TE)
            sm.x_s[cur ^ 1][bb][xi] =
                enc_x[(size_t)(b0g + bb) * (TE * XDIM) + (s + 1) * XDIM + xi];
        step3(c, bias, h, bs, pp, sm.hbuf, sm.x_s[cur]);
        pp ^= 1;
    }

    // ---------------- decoder init ----------------
    if (t < BT) {
        float vf  = v[b0g + t];
        float rvf = 1.0f / vf;
        sm.vf_s[t]  = vf;
        sm.rvf_s[t] = rvf;
        sm.z_s[t]   = enc_z[(size_t)(b0g + t) * TE + (TE - 1)] * rvf;
    }
    __syncthreads();

    // ---------------- decoder ----------------
    for (int s = 0; s < TD; s++) {
        {
            float xv;
            if (xi == 0) xv = sm.z_s[bb];
            else xv = dec_x[(size_t)(b0g + bb) * (TD * (XDIM - 1)) + s * (XDIM - 1) + (xi - 1)];
            sm.x_s[0][bb][xi] = xv;
        }
        __syncthreads();

        step3(c, bias, h, bs, pp, sm.hbuf, sm.x_s[0]);

        if (t < BT) {
            float m  = sm.bm_ba[0];
            float ap = sm.bm_ba[1];
            const float* hrow = &sm.hbuf[2][pp ^ 1][t][0];
#pragma unroll
            for (int kk = 0; kk < HH; kk++) {
                int k = (kk + t) & 63;       // bank-conflict-free rotation
                float hv = hrow[k];
                m  = fmaf(hv, sm.wm_s[k], m);
                ap = fmaf(hv, sm.wa_s[k], ap);
            }
            float vf = sm.vf_s[t];
            m *= vf;
            float sp = fmaxf(ap, 0.0f) + log1pf(__expf(-fabsf(ap)));
            float a  = sp * vf;
            float zs = fmaf(a, eps[(size_t)(b0g + t) * TD + s], m);
            out[(size_t)(b0g + t) * TD + s] = zs;
            sm.z_s[t] = zs * sm.rvf_s[t];
        }
        pp ^= 1;
        __syncthreads();   // z_s ready before next step's x loader
    }
}

// ---------------------------------------------------------------------------
// Input order: enc_x, enc_z, dec_x, v, eps,
//   W_ih0, W_hh0, b0, W_ih1, W_hh1, b1, W_ih2, W_hh2, b2, w_m, b_m, w_a, b_a
// ---------------------------------------------------------------------------
extern "C" void kernel_launch(void* const* d_in, const int* in_sizes, int n_in,
                              void* d_out, int out_size) {
    (void)in_sizes; (void)n_in; (void)out_size;
    const float* enc_x = (const float*)d_in[0];
    const float* enc_z = (const float*)d_in[1];
    const float* dec_x = (const float*)d_in[2];
    const float* v     = (const float*)d_in[3];
    const float* eps   = (const float*)d_in[4];
    const float* Wih0  = (const float*)d_in[5];
    const float* Whh0  = (const float*)d_in[6];
    const float* b0    = (const float*)d_in[7];
    const float* Wih1  = (const float*)d_in[8];
    const float* Whh1  = (const float*)d_in[9];
    const float* b1    = (const float*)d_in[10];
    const float* Wih2  = (const float*)d_in[11];
    const float* Whh2  = (const float*)d_in[12];
    const float* b2    = (const float*)d_in[13];
    const float* w_m   = (const float*)d_in[14];
    const float* b_m   = (const float*)d_in[15];
    const float* w_a   = (const float*)d_in[16];
    const float* b_a   = (const float*)d_in[17];
    float* out = (float*)d_out;

    // >48KB dynamic smem: opt in (idempotent; capture-safe)
    cudaFuncSetAttribute(lstm_seq_kernel,
                         cudaFuncAttributeMaxDynamicSharedMemorySize,
                         (int)sizeof(Smem));

    const int total = NROWS * 256 * 4;
    prep_weights<<<(total + 255) / 256, 256>>>(Wih0, Whh0, Wih1, Whh1, Wih2, Whh2);
    lstm_seq_kernel<<<BTOT / BT, NTHR, sizeof(Smem)>>>(enc_x, enc_z, dec_x, v, eps,
                                                       b0, b1, b2, w_m, b_m, w_a, b_a, out);
}